// round 1
// baseline (speedup 1.0000x reference)
#include <cuda_runtime.h>

// GraphAttentionLayer: B=8, N=2048, Fin=Fout=256
//   Wh = h @ W^T                    (kernel 1)
//   f1 = Wh@a1, f2 = Wh@a2          (kernel 2)
//   w_ij = adj_ij ? exp(leaky(f1_i + f2_j)) : 0   (no max-subtraction: |e| < ~15)
//   out_i = (sum_j w_ij * Wh_j) / (sum_j w_ij)    (kernel 3, fused masked GEMM)

#define NROW   2048
#define FDIM   256
#define NBATCH 8

#define BM  128   // rows per block tile
#define BN  128   // cols per block tile
#define KJ  32    // j-chunk (attention kernel)
#define BK  32    // k-chunk (Wh GEMM)
#define WTS 132   // padded smem stride (128 + 4) -> conflict-free transposed stores

typedef unsigned long long ull;

// -------- scratch (no allocations allowed; __device__ globals) --------
__device__ float g_Wh[NBATCH * NROW * FDIM];   // 16.8 MB
__device__ float g_f1[NBATCH * NROW];
__device__ float g_f2[NBATCH * NROW];

// -------- packed fp32x2 helpers (Blackwell FFMA2: 2x fp32 rate) --------
__device__ __forceinline__ ull pack2(float lo, float hi) {
    ull r; asm("mov.b64 %0, {%1, %2};" : "=l"(r) : "f"(lo), "f"(hi)); return r;
}
__device__ __forceinline__ float2 unpack2(ull v) {
    float2 f; asm("mov.b64 {%0, %1}, %2;" : "=f"(f.x), "=f"(f.y) : "l"(v)); return f;
}
__device__ __forceinline__ ull ffma2(ull a, ull b, ull c) {
    ull d; asm("fma.rn.f32x2 %0, %1, %2, %3;" : "=l"(d) : "l"(a), "l"(b), "l"(c)); return d;
}

// =====================================================================
// Kernel 1: Wh[bn][o] = sum_f h[bn][f] * W[o][f]
// 128x128 block tile, 8x8 thread tile (split 4+4), double-buffered smem.
// =====================================================================
__global__ void __launch_bounds__(256) wh_gemm_kernel(
    const float* __restrict__ h, const float* __restrict__ W,
    float* __restrict__ Wh)
{
    extern __shared__ float sm[];
    float* As = sm;                    // [2][BK][WTS]  h  transposed: As[f][n]
    float* Bs = sm + 2 * BK * WTS;     // [2][BK][WTS]  W  transposed: Bs[f][o]

    const int t  = threadIdx.x;
    const int n0 = blockIdx.x * BM;
    const int o0 = blockIdx.y * BN;
    const int fg = t & 7,  rg = t >> 3;   // loader roles: 4 f x 4 rows
    const int tx = t & 15, ty = t >> 4;   // fma roles: 8 cols x 8 rows

    const float* hp = h + (size_t)(n0 + rg * 4) * FDIM + fg * 4;
    const float* wp = W + (size_t)(o0 + rg * 4) * FDIM + fg * 4;

    ull acc[32];
#pragma unroll
    for (int i = 0; i < 32; i++) acc[i] = 0ULL;

    float4 hr[4], wr[4];

    auto ldg = [&](int it) {
        const int f0 = it * BK;
#pragma unroll
        for (int rl = 0; rl < 4; rl++) {
            hr[rl] = *(const float4*)(hp + (size_t)rl * FDIM + f0);
            wr[rl] = *(const float4*)(wp + (size_t)rl * FDIM + f0);
        }
    };
    auto sts = [&](int buf) {
        float* ab = As + buf * BK * WTS;
        float* bb = Bs + buf * BK * WTS;
#pragma unroll
        for (int fl = 0; fl < 4; fl++) {
            float4 sa = make_float4(((const float*)&hr[0])[fl], ((const float*)&hr[1])[fl],
                                    ((const float*)&hr[2])[fl], ((const float*)&hr[3])[fl]);
            *(float4*)&ab[(fg * 4 + fl) * WTS + rg * 4] = sa;
            float4 sb = make_float4(((const float*)&wr[0])[fl], ((const float*)&wr[1])[fl],
                                    ((const float*)&wr[2])[fl], ((const float*)&wr[3])[fl]);
            *(float4*)&bb[(fg * 4 + fl) * WTS + rg * 4] = sb;
        }
    };
    auto fma_tile = [&](int buf) {
        const float* ab = As + buf * BK * WTS;
        const float* bb = Bs + buf * BK * WTS;
#pragma unroll 8
        for (int k = 0; k < BK; k++) {
            float4 alo = *(const float4*)&ab[k * WTS + ty * 4];
            float4 ahi = *(const float4*)&ab[k * WTS + 64 + ty * 4];
            ulonglong2 b0 = *(const ulonglong2*)&bb[k * WTS + tx * 4];
            ulonglong2 b1 = *(const ulonglong2*)&bb[k * WTS + 64 + tx * 4];
            float as8[8] = {alo.x, alo.y, alo.z, alo.w, ahi.x, ahi.y, ahi.z, ahi.w};
#pragma unroll
            for (int r = 0; r < 8; r++) {
                ull ap = pack2(as8[r], as8[r]);
                acc[r * 4 + 0] = ffma2(ap, b0.x, acc[r * 4 + 0]);
                acc[r * 4 + 1] = ffma2(ap, b0.y, acc[r * 4 + 1]);
                acc[r * 4 + 2] = ffma2(ap, b1.x, acc[r * 4 + 2]);
                acc[r * 4 + 3] = ffma2(ap, b1.y, acc[r * 4 + 3]);
            }
        }
    };

    ldg(0); sts(0); __syncthreads();
    const int NIT = FDIM / BK;   // 8
    for (int it = 0; it < NIT; it++) {
        if (it + 1 < NIT) ldg(it + 1);
        fma_tile(it & 1);
        if (it + 1 < NIT) sts((it + 1) & 1);
        __syncthreads();
    }

    float* op = Wh + (size_t)n0 * FDIM + o0 + tx * 4;
#pragma unroll
    for (int r = 0; r < 8; r++) {
        const int row = ty * 4 + (r & 3) + ((r >> 2) << 6);
        float2 v0 = unpack2(acc[r * 4 + 0]);
        float2 v1 = unpack2(acc[r * 4 + 1]);
        float2 v2 = unpack2(acc[r * 4 + 2]);
        float2 v3 = unpack2(acc[r * 4 + 3]);
        *(float4*)(op + (size_t)row * FDIM)      = make_float4(v0.x, v0.y, v1.x, v1.y);
        *(float4*)(op + (size_t)row * FDIM + 64) = make_float4(v2.x, v2.y, v3.x, v3.y);
    }
}

// =====================================================================
// Kernel 2: f1[row] = dot(Wh[row], a1), f2[row] = dot(Wh[row], a2)
// one warp per row
// =====================================================================
__global__ void __launch_bounds__(256) fvec_kernel(
    const float* __restrict__ Wh, const float* __restrict__ a,
    float* __restrict__ f1, float* __restrict__ f2)
{
    const int row  = blockIdx.x * 8 + (threadIdx.x >> 5);
    const int lane = threadIdx.x & 31;
    const float4* wr = (const float4*)(Wh + (size_t)row * FDIM);
    const float4* a1 = (const float4*)a;
    const float4* a2 = (const float4*)(a + FDIM);

    float4 x0 = wr[lane], x1 = wr[lane + 32];
    float4 p0 = a1[lane], p1 = a1[lane + 32];
    float4 q0 = a2[lane], q1 = a2[lane + 32];

    float s1 = x0.x * p0.x + x0.y * p0.y + x0.z * p0.z + x0.w * p0.w
             + x1.x * p1.x + x1.y * p1.y + x1.z * p1.z + x1.w * p1.w;
    float s2 = x0.x * q0.x + x0.y * q0.y + x0.z * q0.z + x0.w * q0.w
             + x1.x * q1.x + x1.y * q1.y + x1.z * q1.z + x1.w * q1.w;
#pragma unroll
    for (int o = 16; o; o >>= 1) {
        s1 += __shfl_xor_sync(0xFFFFFFFFu, s1, o);
        s2 += __shfl_xor_sync(0xFFFFFFFFu, s2, o);
    }
    if (lane == 0) { f1[row] = s1; f2[row] = s2; }
}

// =====================================================================
// Kernel 3 (main): fused masked-softmax attention x Wh
//   block: 128 rows(i) x 128 cols(o), loop j in chunks of 32.
//   Per chunk: LDG adj tile + Wh tile (staged one iter ahead),
//   compute w on the fly (leaky+exp), transposed store to smem,
//   8x8-per-thread f32x2 outer-product GEMM + row-denominator.
// =====================================================================
__global__ void __launch_bounds__(256) gat_attn_kernel(
    const int*   __restrict__ adj,
    const float* __restrict__ Wh,
    const float* __restrict__ f1g,
    const float* __restrict__ f2g,
    float* __restrict__ out)
{
    extern __shared__ float sm[];
    float* wTs = sm;                     // [2][KJ][WTS]  w transposed: wT[k][i]
    float* bhs = sm + 2 * KJ * WTS;      // [2][KJ][BN]   Wh tile: [k][o]

    const int t  = threadIdx.x;
    const int b  = blockIdx.z;
    const int i0 = blockIdx.x * BM;
    const int cb = blockIdx.y * BN;

    const int kg = t & 7,  rg = t >> 3;   // w-gen roles: 4 k x 4 rows
    const int tx = t & 15, ty = t >> 4;   // fma roles
    const int wc = t & 31, wk = t >> 5;   // Wh-tile loader roles

    const int*   adj_b = adj + (size_t)(b * NROW + i0 + rg * 4) * NROW + kg * 4;
    const float* wh_b  = Wh + (size_t)b * NROW * FDIM + cb + wc * 4;
    const float* f2_b  = f2g + b * NROW + kg * 4;

    const float4 f1v = *(const float4*)(f1g + b * NROW + i0 + rg * 4);

    ull acc[32];
#pragma unroll
    for (int i = 0; i < 32; i++) acc[i] = 0ULL;
    float denom[8] = {0.f, 0.f, 0.f, 0.f, 0.f, 0.f, 0.f, 0.f};

    int4   adjr[4];
    float4 whr[4];
    float4 f2v;

    auto ldg = [&](int it) {
        const int j0 = it * KJ;
#pragma unroll
        for (int rl = 0; rl < 4; rl++)
            adjr[rl] = *(const int4*)(adj_b + (size_t)rl * NROW + j0);
        f2v = *(const float4*)(f2_b + j0);
#pragma unroll
        for (int p = 0; p < 4; p++)
            whr[p] = *(const float4*)(wh_b + (size_t)(j0 + wk + p * 8) * FDIM);
    };

    auto sts = [&](int buf) {
        float* wb = wTs + buf * KJ * WTS;
        float* hb = bhs + buf * KJ * BN;
        float wv[4][4];
#pragma unroll
        for (int rl = 0; rl < 4; rl++) {
            const float fi = ((const float*)&f1v)[rl];
            const int*   a4 = (const int*)&adjr[rl];
            const float* fj = (const float*)&f2v;
#pragma unroll
            for (int kl = 0; kl < 4; kl++) {
                float e = fi + fj[kl];
                e = (e > 0.f) ? e : 0.2f * e;          // LeakyReLU(alpha=0.2)
                wv[rl][kl] = a4[kl] ? __expf(e) : 0.f; // mask -> weight 0
            }
        }
#pragma unroll
        for (int kl = 0; kl < 4; kl++) {
            float4 s = make_float4(wv[0][kl], wv[1][kl], wv[2][kl], wv[3][kl]);
            *(float4*)&wb[(kg * 4 + kl) * WTS + rg * 4] = s;
        }
#pragma unroll
        for (int p = 0; p < 4; p++)
            *(float4*)&hb[(wk + p * 8) * BN + wc * 4] = whr[p];
    };

    auto fma_tile = [&](int buf) {
        const float* wb = wTs + buf * KJ * WTS;
        const float* hb = bhs + buf * KJ * BN;
#pragma unroll 8
        for (int k = 0; k < KJ; k++) {
            float4 wlo = *(const float4*)&wb[k * WTS + ty * 4];
            float4 whi = *(const float4*)&wb[k * WTS + 64 + ty * 4];
            ulonglong2 b0 = *(const ulonglong2*)&hb[k * BN + tx * 4];
            ulonglong2 b1 = *(const ulonglong2*)&hb[k * BN + 64 + tx * 4];
            float ws[8] = {wlo.x, wlo.y, wlo.z, wlo.w, whi.x, whi.y, whi.z, whi.w};
#pragma unroll
            for (int r = 0; r < 8; r++) {
                ull wp = pack2(ws[r], ws[r]);
                acc[r * 4 + 0] = ffma2(wp, b0.x, acc[r * 4 + 0]);
                acc[r * 4 + 1] = ffma2(wp, b0.y, acc[r * 4 + 1]);
                acc[r * 4 + 2] = ffma2(wp, b1.x, acc[r * 4 + 2]);
                acc[r * 4 + 3] = ffma2(wp, b1.y, acc[r * 4 + 3]);
                denom[r] += ws[r];
            }
        }
    };

    ldg(0); sts(0); __syncthreads();
    const int NIT = NROW / KJ;   // 64
    for (int it = 0; it < NIT; it++) {
        if (it + 1 < NIT) ldg(it + 1);
        fma_tile(it & 1);
        if (it + 1 < NIT) sts((it + 1) & 1);
        __syncthreads();
    }

    float* op = out + (size_t)(b * NROW + i0) * FDIM + cb + tx * 4;
#pragma unroll
    for (int r = 0; r < 8; r++) {
        const int   row = ty * 4 + (r & 3) + ((r >> 2) << 6);
        const float inv = 1.0f / denom[r];
        float2 v0 = unpack2(acc[r * 4 + 0]);
        float2 v1 = unpack2(acc[r * 4 + 1]);
        float2 v2 = unpack2(acc[r * 4 + 2]);
        float2 v3 = unpack2(acc[r * 4 + 3]);
        *(float4*)(op + (size_t)row * FDIM) =
            make_float4(v0.x * inv, v0.y * inv, v1.x * inv, v1.y * inv);
        *(float4*)(op + (size_t)row * FDIM + 64) =
            make_float4(v2.x * inv, v2.y * inv, v3.x * inv, v3.y * inv);
    }
}

// =====================================================================
extern "C" void kernel_launch(void* const* d_in, const int* in_sizes, int n_in,
                              void* d_out, int out_size)
{
    const float* h   = (const float*)d_in[0];
    const int*   adj = (const int*)  d_in[1];
    const float* W   = (const float*)d_in[2];
    const float* a   = (const float*)d_in[3];
    float* out = (float*)d_out;

    float *Wh, *f1, *f2;
    cudaGetSymbolAddress((void**)&Wh, g_Wh);
    cudaGetSymbolAddress((void**)&f1, g_f1);
    cudaGetSymbolAddress((void**)&f2, g_f2);

    const int smemA = 4 * BK * WTS * (int)sizeof(float);            // 67584 B
    const int smemB = (2 * KJ * WTS + 2 * KJ * BN) * (int)sizeof(float); // 66560 B
    cudaFuncSetAttribute(wh_gemm_kernel, cudaFuncAttributeMaxDynamicSharedMemorySize, smemA);
    cudaFuncSetAttribute(gat_attn_kernel, cudaFuncAttributeMaxDynamicSharedMemorySize, smemB);

    // 1) Wh = h @ W^T    (grid: 16384/128 row tiles x 256/128 col tiles)
    wh_gemm_kernel<<<dim3(NBATCH * NROW / BM, FDIM / BN), 256, smemA>>>(h, W, Wh);
    // 2) f1, f2
    fvec_kernel<<<NBATCH * NROW / 8, 256>>>(Wh, a, f1, f2);
    // 3) fused attention
    gat_attn_kernel<<<dim3(NROW / BM, FDIM / BN, NBATCH), 256, smemB>>>(adj, Wh, f1, f2, out);
}

// round 3
// speedup vs baseline: 1.5865x; 1.5865x over previous
#include <cuda_runtime.h>
#include <cstdint>

// GraphAttentionLayer: B=8, N=2048, Fin=Fout=256
//  K1: Wh = h @ W^T                 (fp32 CUDA cores, f32x2 FFMA)
//  K2: per-row E1=exp(f1), F1=exp(.2 f1), E2=exp(f2), F2=exp(.2 f2)
//  K3: mma.sync tf32 attention:  out_i = (sum_j w_ij Wh_j) / (sum_j w_ij)
//      w_ij = adj ? (E2_j > 1/E1_i ? E1_i*E2_j : F1_i*F2_j) : 0  (exact leaky+exp)

#define NROW 2048
#define FDIM 256
#define NBATCH 8

#define BM  128
#define BN  128
#define BK  32
#define WTS 132

#define KJ  32
#define NIT (NROW / KJ)   // 64

// K3 smem strides (floats) — chosen for conflict-free fragment LDS
#define WSTR 36    // w tile: addr%32 = 4g+tig -> unique
#define HSTR 136   // Wh tile: addr%32 = 8tig+g -> unique

typedef unsigned long long ull;

// ---------------- scratch ----------------
__device__ float g_Wh[NBATCH * NROW * FDIM];   // 16.8 MB
__device__ float g_E1[NBATCH * NROW], g_F1[NBATCH * NROW];
__device__ float g_E2[NBATCH * NROW], g_F2[NBATCH * NROW];

// ---------------- helpers ----------------
__device__ __forceinline__ ull pack2(float lo, float hi) {
    ull r; asm("mov.b64 %0, {%1, %2};" : "=l"(r) : "f"(lo), "f"(hi)); return r;
}
__device__ __forceinline__ float2 unpack2(ull v) {
    float2 f; asm("mov.b64 {%0, %1}, %2;" : "=f"(f.x), "=f"(f.y) : "l"(v)); return f;
}
__device__ __forceinline__ ull ffma2(ull a, ull b, ull c) {
    ull d; asm("fma.rn.f32x2 %0, %1, %2, %3;" : "=l"(d) : "l"(a), "l"(b), "l"(c)); return d;
}
__device__ __forceinline__ uint32_t to_tf32(float x) {
    uint32_t r; asm("cvt.rna.tf32.f32 %0, %1;" : "=r"(r) : "f"(x)); return r;
}
// m16n8k8 tf32 mma (A row-major, B col-major), fp32 accumulate in-place
__device__ __forceinline__ void mma_tf32(float* d, const uint32_t* a, const uint32_t* b) {
    asm volatile(
        "mma.sync.aligned.m16n8k8.row.col.f32.tf32.tf32.f32 "
        "{%0,%1,%2,%3}, {%4,%5,%6,%7}, {%8,%9}, {%0,%1,%2,%3};"
        : "+f"(d[0]), "+f"(d[1]), "+f"(d[2]), "+f"(d[3])
        : "r"(a[0]), "r"(a[1]), "r"(a[2]), "r"(a[3]), "r"(b[0]), "r"(b[1]));
}

// =====================================================================
// Kernel 1: Wh = h @ W^T (fp32, f32x2 FFMA), 128x128 tile, double buffer
// =====================================================================
__global__ void __launch_bounds__(256) wh_gemm_kernel(
    const float* __restrict__ h, const float* __restrict__ W,
    float* __restrict__ Wh)
{
    extern __shared__ float sm[];
    float* As = sm;
    float* Bs = sm + 2 * BK * WTS;

    const int t  = threadIdx.x;
    const int n0 = blockIdx.x * BM;
    const int o0 = blockIdx.y * BN;
    const int fg = t & 7,  rg = t >> 3;
    const int tx = t & 15, ty = t >> 4;

    const float* hp = h + (size_t)(n0 + rg * 4) * FDIM + fg * 4;
    const float* wp = W + (size_t)(o0 + rg * 4) * FDIM + fg * 4;

    ull acc[32];
#pragma unroll
    for (int i = 0; i < 32; i++) acc[i] = 0ULL;

    float4 hr[4], wr[4];

    auto ldg = [&](int it) {
        const int f0 = it * BK;
#pragma unroll
        for (int rl = 0; rl < 4; rl++) {
            hr[rl] = *(const float4*)(hp + (size_t)rl * FDIM + f0);
            wr[rl] = *(const float4*)(wp + (size_t)rl * FDIM + f0);
        }
    };
    auto sts = [&](int buf) {
        float* ab = As + buf * BK * WTS;
        float* bb = Bs + buf * BK * WTS;
#pragma unroll
        for (int fl = 0; fl < 4; fl++) {
            float4 sa = make_float4(((const float*)&hr[0])[fl], ((const float*)&hr[1])[fl],
                                    ((const float*)&hr[2])[fl], ((const float*)&hr[3])[fl]);
            *(float4*)&ab[(fg * 4 + fl) * WTS + rg * 4] = sa;
            float4 sb = make_float4(((const float*)&wr[0])[fl], ((const float*)&wr[1])[fl],
                                    ((const float*)&wr[2])[fl], ((const float*)&wr[3])[fl]);
            *(float4*)&bb[(fg * 4 + fl) * WTS + rg * 4] = sb;
        }
    };
    auto fma_tile = [&](int buf) {
        const float* ab = As + buf * BK * WTS;
        const float* bb = Bs + buf * BK * WTS;
#pragma unroll 8
        for (int k = 0; k < BK; k++) {
            float4 alo = *(const float4*)&ab[k * WTS + ty * 4];
            float4 ahi = *(const float4*)&ab[k * WTS + 64 + ty * 4];
            ulonglong2 b0 = *(const ulonglong2*)&bb[k * WTS + tx * 4];
            ulonglong2 b1 = *(const ulonglong2*)&bb[k * WTS + 64 + tx * 4];
            float as8[8] = {alo.x, alo.y, alo.z, alo.w, ahi.x, ahi.y, ahi.z, ahi.w};
#pragma unroll
            for (int r = 0; r < 8; r++) {
                ull ap = pack2(as8[r], as8[r]);
                acc[r * 4 + 0] = ffma2(ap, b0.x, acc[r * 4 + 0]);
                acc[r * 4 + 1] = ffma2(ap, b0.y, acc[r * 4 + 1]);
                acc[r * 4 + 2] = ffma2(ap, b1.x, acc[r * 4 + 2]);
                acc[r * 4 + 3] = ffma2(ap, b1.y, acc[r * 4 + 3]);
            }
        }
    };

    ldg(0); sts(0); __syncthreads();
    const int NITK = FDIM / BK;   // 8
    for (int it = 0; it < NITK; it++) {
        if (it + 1 < NITK) ldg(it + 1);
        fma_tile(it & 1);
        if (it + 1 < NITK) sts((it + 1) & 1);
        __syncthreads();
    }

    float* op = Wh + (size_t)n0 * FDIM + o0 + tx * 4;
#pragma unroll
    for (int r = 0; r < 8; r++) {
        const int row = ty * 4 + (r & 3) + ((r >> 2) << 6);
        float2 v0 = unpack2(acc[r * 4 + 0]);
        float2 v1 = unpack2(acc[r * 4 + 1]);
        float2 v2 = unpack2(acc[r * 4 + 2]);
        float2 v3 = unpack2(acc[r * 4 + 3]);
        *(float4*)(op + (size_t)row * FDIM)      = make_float4(v0.x, v0.y, v1.x, v1.y);
        *(float4*)(op + (size_t)row * FDIM + 64) = make_float4(v2.x, v2.y, v3.x, v3.y);
    }
}

// =====================================================================
// Kernel 2: per-row f1,f2 -> E1,F1,E2,F2
// =====================================================================
__global__ void __launch_bounds__(256) fvec_kernel(
    const float* __restrict__ Wh, const float* __restrict__ a,
    float* __restrict__ E1, float* __restrict__ F1,
    float* __restrict__ E2, float* __restrict__ F2)
{
    const int row  = blockIdx.x * 8 + (threadIdx.x >> 5);
    const int lane = threadIdx.x & 31;
    const float4* wr = (const float4*)(Wh + (size_t)row * FDIM);
    const float4* a1 = (const float4*)a;
    const float4* a2 = (const float4*)(a + FDIM);

    float4 x0 = wr[lane], x1 = wr[lane + 32];
    float4 p0 = a1[lane], p1 = a1[lane + 32];
    float4 q0 = a2[lane], q1 = a2[lane + 32];

    float s1 = x0.x * p0.x + x0.y * p0.y + x0.z * p0.z + x0.w * p0.w
             + x1.x * p1.x + x1.y * p1.y + x1.z * p1.z + x1.w * p1.w;
    float s2 = x0.x * q0.x + x0.y * q0.y + x0.z * q0.z + x0.w * q0.w
             + x1.x * q1.x + x1.y * q1.y + x1.z * q1.z + x1.w * q1.w;
#pragma unroll
    for (int o = 16; o; o >>= 1) {
        s1 += __shfl_xor_sync(0xFFFFFFFFu, s1, o);
        s2 += __shfl_xor_sync(0xFFFFFFFFu, s2, o);
    }
    if (lane == 0) {
        E1[row] = __expf(s1);
        F1[row] = __expf(0.2f * s1);
        E2[row] = __expf(s2);
        F2[row] = __expf(0.2f * s2);
    }
}

// =====================================================================
// Kernel 3: tf32 mma.sync attention. Block 128i x 128o, K=2048 in j-chunks
// of 32. w generated on the fly into smem (tf32-rounded), single sync/chunk.
// =====================================================================
// smem floats:
//   wS : [2][128][WSTR]  offset 0           (2*128*36  = 9216 f)
//   hS : [2][32][HSTR]   offset 9216        (2*32*136  = 8704 f)
//   den: [256]           offset 17920
#define SM_HS  9216
#define SM_DEN 17920
#define SM_SZ3 ((17920 + 256) * 4)

__global__ void __launch_bounds__(256) attn_mma_kernel(
    const int*   __restrict__ adj,
    const float* __restrict__ Wh,
    const float* __restrict__ E1, const float* __restrict__ F1,
    const float* __restrict__ E2, const float* __restrict__ F2,
    float* __restrict__ out)
{
    extern __shared__ float sm[];
    float* smW = sm;
    float* smH = sm + SM_HS;
    float* den = sm + SM_DEN;

    const int t   = threadIdx.x;
    const int wid = t >> 5, lid = t & 31;
    const int bz  = blockIdx.z;
    const int i0  = blockIdx.x * BM;
    const int o0  = blockIdx.y * BN;

    // gen roles: row r, j-half hf (16 j's)
    const int r = t >> 1, hf = t & 1;
    // Wh loader roles
    const int wc = t & 31, wk = t >> 5;
    // mma roles
    const int wi = wid & 3, wo = wid >> 2;       // warp tile: rows wi*32, cols wo*64
    const int g = lid >> 2, tig = lid & 3;

    const int row_g = bz * NROW + i0 + r;
    const int*   adjp = adj + (size_t)row_g * NROW + hf * 16;
    const float* e2p  = E2 + bz * NROW + hf * 16;
    const float* f2p  = F2 + bz * NROW + hf * 16;
    const float* whp  = Wh + (size_t)(bz * NROW + wk) * FDIM + o0 + wc * 4;
    const float  E1r  = E1[row_g], F1r = F1[row_g];
    const float  tinv = __frcp_rn(E1r);          // s>0  <=>  E2_j > 1/E1_i

    float d[2][8][4];
#pragma unroll
    for (int mi = 0; mi < 2; mi++)
#pragma unroll
        for (int ni = 0; ni < 8; ni++)
#pragma unroll
            for (int q = 0; q < 4; q++) d[mi][ni][q] = 0.f;

    float dn = 0.f;
    int4   adjr[4];
    float4 whr[4];

    auto ldg = [&](int c) {
        const int j0 = c * KJ;
#pragma unroll
        for (int q = 0; q < 4; q++)
            adjr[q] = *(const int4*)(adjp + j0 + q * 4);
#pragma unroll
        for (int p = 0; p < 4; p++)
            whr[p] = *(const float4*)(whp + (size_t)(j0 + p * 8) * FDIM);
    };

    auto gen_sts = [&](int bf, int c) {
        const int j0 = c * KJ;
        float* wb = smW + bf * (BM * WSTR);
        float* hb = smH + bf * (KJ * HSTR);
#pragma unroll
        for (int p = 0; p < 4; p++)
            *(float4*)&hb[(wk + p * 8) * HSTR + wc * 4] = whr[p];
#pragma unroll
        for (int q = 0; q < 4; q++) {
            float4 e2v = *(const float4*)(e2p + j0 + q * 4);
            float4 f2v = *(const float4*)(f2p + j0 + q * 4);
            const int* am = (const int*)&adjr[q];
            float4 wv;
#pragma unroll
            for (int e = 0; e < 4; e++) {
                const float e2 = ((const float*)&e2v)[e];
                const float f2 = ((const float*)&f2v)[e];
                const bool pos = e2 > tinv;
                float w = am[e] ? (pos ? E1r * e2 : F1r * f2) : 0.f;
                w = __uint_as_float(to_tf32(w));
                dn += w;
                ((float*)&wv)[e] = w;
            }
            *(float4*)&wb[r * WSTR + hf * 16 + q * 4] = wv;
        }
    };

    auto mma_phase = [&](int bf) {
        const float* wb = smW + bf * (BM * WSTR);
        const float* hb = smH + bf * (KJ * HSTR);
#pragma unroll
        for (int ks = 0; ks < 4; ks++) {
            uint32_t afr[2][4];
#pragma unroll
            for (int mi = 0; mi < 2; mi++) {
                const int row = wi * 32 + mi * 16 + g;
                const int kc  = ks * 8 + tig;
                afr[mi][0] = __float_as_uint(wb[row * WSTR + kc]);
                afr[mi][1] = __float_as_uint(wb[(row + 8) * WSTR + kc]);
                afr[mi][2] = __float_as_uint(wb[row * WSTR + kc + 4]);
                afr[mi][3] = __float_as_uint(wb[(row + 8) * WSTR + kc + 4]);
            }
            uint32_t bfr[8][2];
#pragma unroll
            for (int ni = 0; ni < 8; ni++) {
                const int col = wo * 64 + ni * 8 + g;
                bfr[ni][0] = to_tf32(hb[(ks * 8 + tig) * HSTR + col]);
                bfr[ni][1] = to_tf32(hb[(ks * 8 + tig + 4) * HSTR + col]);
            }
#pragma unroll
            for (int mi = 0; mi < 2; mi++)
#pragma unroll
                for (int ni = 0; ni < 8; ni++)
                    mma_tf32(d[mi][ni], afr[mi], bfr[ni]);
        }
    };

    ldg(0);
    for (int c = 0; c < NIT; c++) {
        const int bf = c & 1;
        gen_sts(bf, c);
        __syncthreads();
        if (c + 1 < NIT) ldg(c + 1);
        mma_phase(bf);
        // next gen writes the other buffer; sync at next iter guards mma reads
    }

    den[t] = dn;                      // den[2*row + hf]
    __syncthreads();

    // epilogue: D frag (mi,ni): c0/c1 at row g, cols tig*2/+1; c2/c3 at row g+8
#pragma unroll
    for (int mi = 0; mi < 2; mi++) {
        const int r0 = wi * 32 + mi * 16 + g;
        const int r1 = r0 + 8;
        const float inv0 = 1.0f / (den[2 * r0] + den[2 * r0 + 1]);
        const float inv1 = 1.0f / (den[2 * r1] + den[2 * r1 + 1]);
        float* op0 = out + (size_t)(bz * NROW + i0 + r0) * FDIM + o0 + wo * 64 + tig * 2;
        float* op1 = out + (size_t)(bz * NROW + i0 + r1) * FDIM + o0 + wo * 64 + tig * 2;
#pragma unroll
        for (int ni = 0; ni < 8; ni++) {
            *(float2*)(op0 + ni * 8) = make_float2(d[mi][ni][0] * inv0, d[mi][ni][1] * inv0);
            *(float2*)(op1 + ni * 8) = make_float2(d[mi][ni][2] * inv1, d[mi][ni][3] * inv1);
        }
    }
}

// =====================================================================
extern "C" void kernel_launch(void* const* d_in, const int* in_sizes, int n_in,
                              void* d_out, int out_size)
{
    const float* h   = (const float*)d_in[0];
    const int*   adj = (const int*)  d_in[1];
    const float* W   = (const float*)d_in[2];
    const float* a   = (const float*)d_in[3];
    float* out = (float*)d_out;

    float *Wh, *E1, *F1, *E2, *F2;
    cudaGetSymbolAddress((void**)&Wh, g_Wh);
    cudaGetSymbolAddress((void**)&E1, g_E1);
    cudaGetSymbolAddress((void**)&F1, g_F1);
    cudaGetSymbolAddress((void**)&E2, g_E2);
    cudaGetSymbolAddress((void**)&F2, g_F2);

    const int smemA = 4 * BK * WTS * (int)sizeof(float);   // 67584
    cudaFuncSetAttribute(wh_gemm_kernel,  cudaFuncAttributeMaxDynamicSharedMemorySize, smemA);
    cudaFuncSetAttribute(attn_mma_kernel, cudaFuncAttributeMaxDynamicSharedMemorySize, SM_SZ3);

    wh_gemm_kernel<<<dim3(NBATCH * NROW / BM, FDIM / BN), 256, smemA>>>(h, W, Wh);
    fvec_kernel<<<NBATCH * NROW / 8, 256>>>(Wh, a, E1, F1, E2, F2);
    attn_mma_kernel<<<dim3(NROW / BM, FDIM / BN, NBATCH), 256, SM_SZ3>>>(
        adj, Wh, E1, F1, E2, F2, out);
}

// round 4
// speedup vs baseline: 2.2900x; 1.4435x over previous
#include <cuda_runtime.h>
#include <cuda_fp16.h>
#include <cstdint>

// GraphAttentionLayer: B=8, N=2048, Fin=Fout=256
//  K1: Wh = h @ W^T           (mma.sync tf32; writes Wh fp32 + Whh fp16)
//  K2: per-row E1=exp(f1), F1=exp(.2 f1), E2=exp(f2), F2=exp(.2 f2)
//  K3: mma.sync fp16 m16n8k16: out_i = (sum_j w_ij Wh_j) / (sum_j w_ij)
//      w_ij = adj ? (E2_j > 1/E1_i ? E1_i*E2_j : F1_i*F2_j) : 0  (exact leaky+exp)

#define NROW   2048
#define FDIM   256
#define NBATCH 8
#define NTOT   (NBATCH * NROW)

// K1 tiling (128x128 tile, K-chunks of 32, u32 smem stride 36)
#define K1ST 36
// K3 tiling
#define KJ  32
#define NIT (NROW / KJ)   // 64
#define AST 40            // halves stride of w tile row (32 + 8 pad)
#define BST 136           // halves stride of Wh tile k-row (128 + 8 pad)

// ---------------- scratch ----------------
__device__ float  g_Wh [NTOT * FDIM];   // fp32 (tf32-product) for K2
__device__ __half g_Whh[NTOT * FDIM];   // fp16 copy for K3
__device__ float g_E1[NTOT], g_F1[NTOT], g_E2[NTOT], g_F2[NTOT];

// ---------------- helpers ----------------
__device__ __forceinline__ uint32_t to_tf32(float x) {
    uint32_t r; asm("cvt.rna.tf32.f32 %0, %1;" : "=r"(r) : "f"(x)); return r;
}
__device__ __forceinline__ void mma_tf32(float* d, const uint32_t* a, const uint32_t* b) {
    asm volatile(
        "mma.sync.aligned.m16n8k8.row.col.f32.tf32.tf32.f32 "
        "{%0,%1,%2,%3}, {%4,%5,%6,%7}, {%8,%9}, {%0,%1,%2,%3};"
        : "+f"(d[0]), "+f"(d[1]), "+f"(d[2]), "+f"(d[3])
        : "r"(a[0]), "r"(a[1]), "r"(a[2]), "r"(a[3]), "r"(b[0]), "r"(b[1]));
}
__device__ __forceinline__ void mma_f16(float* d, const uint32_t* a, const uint32_t* b) {
    asm volatile(
        "mma.sync.aligned.m16n8k16.row.col.f32.f16.f16.f32 "
        "{%0,%1,%2,%3}, {%4,%5,%6,%7}, {%8,%9}, {%0,%1,%2,%3};"
        : "+f"(d[0]), "+f"(d[1]), "+f"(d[2]), "+f"(d[3])
        : "r"(a[0]), "r"(a[1]), "r"(a[2]), "r"(a[3]), "r"(b[0]), "r"(b[1]));
}
__device__ __forceinline__ void ldm_x4(uint32_t* r, const void* p) {
    uint32_t a = (uint32_t)__cvta_generic_to_shared(p);
    asm volatile("ldmatrix.sync.aligned.m8n8.x4.shared.b16 {%0,%1,%2,%3}, [%4];"
                 : "=r"(r[0]), "=r"(r[1]), "=r"(r[2]), "=r"(r[3]) : "r"(a));
}
__device__ __forceinline__ void ldm_x4_t(uint32_t* r, const void* p) {
    uint32_t a = (uint32_t)__cvta_generic_to_shared(p);
    asm volatile("ldmatrix.sync.aligned.m8n8.x4.trans.shared.b16 {%0,%1,%2,%3}, [%4];"
                 : "=r"(r[0]), "=r"(r[1]), "=r"(r[2]), "=r"(r[3]) : "r"(a));
}

// =====================================================================
// Kernel 1: Wh = h @ W^T via tf32 mma.sync. 128x128 tile, BK=32, dbuf.
// A = h rows (row-major m x k), B = W rows (col-major k x n == W[o][f]).
// =====================================================================
__global__ void __launch_bounds__(256) wh_mma_kernel(
    const float* __restrict__ h, const float* __restrict__ W,
    float* __restrict__ Wh, __half* __restrict__ Whh)
{
    extern __shared__ uint32_t sm1[];
    uint32_t* sA = sm1;                      // [2][128][K1ST]
    uint32_t* sB = sm1 + 2 * 128 * K1ST;     // [2][128][K1ST]

    const int t = threadIdx.x, wid = t >> 5, lid = t & 31;
    const int n0 = blockIdx.x * 128, o0 = blockIdx.y * 128;
    const int r = t >> 1, hfq = t & 1;          // loader: row r, f-half hfq*16
    const int wi = wid & 3, wo = wid >> 2;      // warp tile rows wi*32, cols wo*64
    const int g = lid >> 2, tig = lid & 3;

    const float* hp = h + (size_t)(n0 + r) * FDIM + hfq * 16;
    const float* wp = W + (size_t)(o0 + r) * FDIM + hfq * 16;

    float d[2][8][4];
#pragma unroll
    for (int mi = 0; mi < 2; mi++)
#pragma unroll
        for (int ni = 0; ni < 8; ni++)
#pragma unroll
            for (int q = 0; q < 4; q++) d[mi][ni][q] = 0.f;

    float4 hr[4], wr[4];

    auto ldg = [&](int it) {
        const int f0 = it * 32;
#pragma unroll
        for (int q = 0; q < 4; q++) {
            hr[q] = *(const float4*)(hp + f0 + q * 4);
            wr[q] = *(const float4*)(wp + f0 + q * 4);
        }
    };
    auto sts = [&](int bf) {
        uint32_t* ab = sA + bf * 128 * K1ST + r * K1ST + hfq * 16;
        uint32_t* bb = sB + bf * 128 * K1ST + r * K1ST + hfq * 16;
#pragma unroll
        for (int q = 0; q < 4; q++) {
            uint4 va = make_uint4(to_tf32(hr[q].x), to_tf32(hr[q].y),
                                  to_tf32(hr[q].z), to_tf32(hr[q].w));
            *(uint4*)(ab + q * 4) = va;
            uint4 vb = make_uint4(to_tf32(wr[q].x), to_tf32(wr[q].y),
                                  to_tf32(wr[q].z), to_tf32(wr[q].w));
            *(uint4*)(bb + q * 4) = vb;
        }
    };
    auto mma_phase = [&](int bf) {
        const uint32_t* A = sA + bf * 128 * K1ST;
        const uint32_t* B = sB + bf * 128 * K1ST;
#pragma unroll
        for (int ks = 0; ks < 4; ks++) {
            uint32_t af[2][4];
#pragma unroll
            for (int mi = 0; mi < 2; mi++) {
                const int row = wi * 32 + mi * 16 + g;
                const int kc  = ks * 8 + tig;
                af[mi][0] = A[row * K1ST + kc];
                af[mi][1] = A[(row + 8) * K1ST + kc];
                af[mi][2] = A[row * K1ST + kc + 4];
                af[mi][3] = A[(row + 8) * K1ST + kc + 4];
            }
            uint32_t bfr[8][2];
#pragma unroll
            for (int ni = 0; ni < 8; ni++) {
                const int col = wo * 64 + ni * 8 + g;
                const int kc  = ks * 8 + tig;
                bfr[ni][0] = B[col * K1ST + kc];
                bfr[ni][1] = B[col * K1ST + kc + 4];
            }
#pragma unroll
            for (int mi = 0; mi < 2; mi++)
#pragma unroll
                for (int ni = 0; ni < 8; ni++)
                    mma_tf32(d[mi][ni], af[mi], bfr[ni]);
        }
    };

    ldg(0); sts(0); __syncthreads();
    for (int it = 0; it < 8; it++) {
        if (it + 1 < 8) ldg(it + 1);
        mma_phase(it & 1);
        if (it + 1 < 8) sts((it + 1) & 1);
        __syncthreads();
    }

    // epilogue: write Wh fp32 + Whh fp16
#pragma unroll
    for (int mi = 0; mi < 2; mi++) {
        const int r0 = wi * 32 + mi * 16 + g;
        const int r1 = r0 + 8;
        float*  o0p = Wh + (size_t)(n0 + r0) * FDIM + o0 + wo * 64 + tig * 2;
        float*  o1p = Wh + (size_t)(n0 + r1) * FDIM + o0 + wo * 64 + tig * 2;
        __half* h0p = Whh + (size_t)(n0 + r0) * FDIM + o0 + wo * 64 + tig * 2;
        __half* h1p = Whh + (size_t)(n0 + r1) * FDIM + o0 + wo * 64 + tig * 2;
#pragma unroll
        for (int ni = 0; ni < 8; ni++) {
            *(float2*)(o0p + ni * 8) = make_float2(d[mi][ni][0], d[mi][ni][1]);
            *(float2*)(o1p + ni * 8) = make_float2(d[mi][ni][2], d[mi][ni][3]);
            *(__half2*)(h0p + ni * 8) =
                __float22half2_rn(make_float2(d[mi][ni][0], d[mi][ni][1]));
            *(__half2*)(h1p + ni * 8) =
                __float22half2_rn(make_float2(d[mi][ni][2], d[mi][ni][3]));
        }
    }
}

// =====================================================================
// Kernel 2: per-row f1,f2 -> E1,F1,E2,F2
// =====================================================================
__global__ void __launch_bounds__(256) fvec_kernel(
    const float* __restrict__ Wh, const float* __restrict__ a,
    float* __restrict__ E1, float* __restrict__ F1,
    float* __restrict__ E2, float* __restrict__ F2)
{
    const int row  = blockIdx.x * 8 + (threadIdx.x >> 5);
    const int lane = threadIdx.x & 31;
    const float4* wr = (const float4*)(Wh + (size_t)row * FDIM);
    const float4* a1 = (const float4*)a;
    const float4* a2 = (const float4*)(a + FDIM);

    float4 x0 = wr[lane], x1 = wr[lane + 32];
    float4 p0 = a1[lane], p1 = a1[lane + 32];
    float4 q0 = a2[lane], q1 = a2[lane + 32];

    float s1 = x0.x * p0.x + x0.y * p0.y + x0.z * p0.z + x0.w * p0.w
             + x1.x * p1.x + x1.y * p1.y + x1.z * p1.z + x1.w * p1.w;
    float s2 = x0.x * q0.x + x0.y * q0.y + x0.z * q0.z + x0.w * q0.w
             + x1.x * q1.x + x1.y * q1.y + x1.z * q1.z + x1.w * q1.w;
#pragma unroll
    for (int o = 16; o; o >>= 1) {
        s1 += __shfl_xor_sync(0xFFFFFFFFu, s1, o);
        s2 += __shfl_xor_sync(0xFFFFFFFFu, s2, o);
    }
    if (lane == 0) {
        E1[row] = __expf(s1);
        F1[row] = __expf(0.2f * s1);
        E2[row] = __expf(s2);
        F2[row] = __expf(0.2f * s2);
    }
}

// =====================================================================
// Kernel 3: fp16 m16n8k16 mma attention. Block 128i x 128o, j-chunks of 32.
// w generated fp32-exact, rounded to fp16; B tile = Whh fp16 (ldmatrix.trans).
// =====================================================================
__global__ void __launch_bounds__(256) attn_f16_kernel(
    const int*  __restrict__ adj,
    const __half* __restrict__ Whh,
    const float* __restrict__ E1, const float* __restrict__ F1,
    const float* __restrict__ E2, const float* __restrict__ F2,
    float* __restrict__ out)
{
    extern __shared__ __half smh[];
    __half* smA = smh;                       // [2][128][AST]
    __half* smB = smh + 2 * 128 * AST;       // [2][32][BST]
    float*  den = (float*)(smh + 2 * 128 * AST + 2 * KJ * BST);   // [256]

    const int t = threadIdx.x, wid = t >> 5, lid = t & 31;
    const int bz = blockIdx.z;
    const int i0 = blockIdx.x * 128;
    const int o0 = blockIdx.y * 128;

    const int r = t >> 1, hf = t & 1;            // w-gen: row r, j-half hf*16
    const int krow = t >> 3, kcol = (t & 7) * 16; // B staging roles
    const int wi = wid & 3, wo = wid >> 2;
    const int g = lid >> 2, tig = lid & 3;

    const int row_g = bz * NROW + i0 + r;
    const int*    adjp = adj + (size_t)row_g * NROW + hf * 16;
    const float*  e2p  = E2 + bz * NROW + hf * 16;
    const float*  f2p  = F2 + bz * NROW + hf * 16;
    const __half* whp  = Whh + (size_t)(bz * NROW + krow) * FDIM + o0 + kcol;
    const float   E1r  = E1[row_g], F1r = F1[row_g];
    const float   tinv = __frcp_rn(E1r);         // s>0  <=>  E2_j > 1/E1_i

    float d[2][8][4];
#pragma unroll
    for (int mi = 0; mi < 2; mi++)
#pragma unroll
        for (int ni = 0; ni < 8; ni++)
#pragma unroll
            for (int q = 0; q < 4; q++) d[mi][ni][q] = 0.f;

    float dn = 0.f;
    int4  adjr[4];
    uint4 hh0, hh1;

    auto ldg = [&](int c) {
        const int j0 = c * KJ;
#pragma unroll
        for (int q = 0; q < 4; q++)
            adjr[q] = *(const int4*)(adjp + j0 + q * 4);
        hh0 = *(const uint4*)(whp + (size_t)j0 * FDIM);
        hh1 = *(const uint4*)(whp + (size_t)j0 * FDIM + 8);
    };

    auto gen_sts = [&](int bf, int c) {
        const int j0 = c * KJ;
        // B tile: [k][o] halves, natural layout
        __half* bb = smB + bf * (KJ * BST) + krow * BST + kcol;
        *(uint4*)bb       = hh0;
        *(uint4*)(bb + 8) = hh1;
        // A tile: w halves
        uint32_t h2a[8];
#pragma unroll
        for (int q = 0; q < 4; q++) {
            float4 e2v = *(const float4*)(e2p + j0 + q * 4);
            float4 f2v = *(const float4*)(f2p + j0 + q * 4);
            const int* am = (const int*)&adjr[q];
            float w4[4];
#pragma unroll
            for (int e = 0; e < 4; e++) {
                const float e2 = ((const float*)&e2v)[e];
                const float f2 = ((const float*)&f2v)[e];
                const bool pos = e2 > tinv;
                w4[e] = am[e] ? (pos ? E1r * e2 : F1r * f2) : 0.f;
            }
            __half2 p0 = __float22half2_rn(make_float2(w4[0], w4[1]));
            __half2 p1 = __float22half2_rn(make_float2(w4[2], w4[3]));
            float2 b0 = __half22float2(p0), b1 = __half22float2(p1);
            dn += (b0.x + b0.y) + (b1.x + b1.y);
            h2a[q * 2 + 0] = *(uint32_t*)&p0;
            h2a[q * 2 + 1] = *(uint32_t*)&p1;
        }
        __half* ab = smA + bf * (128 * AST) + r * AST + hf * 16;
        *(uint4*)ab       = *(uint4*)&h2a[0];
        *(uint4*)(ab + 8) = *(uint4*)&h2a[4];
    };

    auto mma_phase = [&](int bf) {
        const __half* A = smA + bf * (128 * AST);
        const __half* B = smB + bf * (KJ * BST);
#pragma unroll
        for (int ks = 0; ks < 2; ks++) {
            uint32_t af[2][4];
#pragma unroll
            for (int mi = 0; mi < 2; mi++)
                ldm_x4(af[mi], A + (wi * 32 + mi * 16 + (lid & 15)) * AST
                               + ks * 16 + (lid >> 4) * 8);
            uint32_t bf4[4][4];
#pragma unroll
            for (int np = 0; np < 4; np++)
                ldm_x4_t(bf4[np], B + (ks * 16 + (lid & 7) + ((lid >> 3) & 1) * 8) * BST
                                  + wo * 64 + np * 16 + (lid >> 4) * 8);
#pragma unroll
            for (int mi = 0; mi < 2; mi++)
#pragma unroll
                for (int ni = 0; ni < 8; ni++)
                    mma_f16(d[mi][ni], af[mi], &bf4[ni >> 1][(ni & 1) * 2]);
        }
    };

    ldg(0);
    for (int c = 0; c < NIT; c++) {
        const int bf = c & 1;
        gen_sts(bf, c);
        __syncthreads();
        if (c + 1 < NIT) ldg(c + 1);
        mma_phase(bf);
    }

    den[t] = dn;                      // den[2*row + hf]
    __syncthreads();

#pragma unroll
    for (int mi = 0; mi < 2; mi++) {
        const int r0 = wi * 32 + mi * 16 + g;
        const int r1 = r0 + 8;
        const float inv0 = 1.0f / (den[2 * r0] + den[2 * r0 + 1]);
        const float inv1 = 1.0f / (den[2 * r1] + den[2 * r1 + 1]);
        float* op0 = out + (size_t)(bz * NROW + i0 + r0) * FDIM + o0 + wo * 64 + tig * 2;
        float* op1 = out + (size_t)(bz * NROW + i0 + r1) * FDIM + o0 + wo * 64 + tig * 2;
#pragma unroll
        for (int ni = 0; ni < 8; ni++) {
            *(float2*)(op0 + ni * 8) = make_float2(d[mi][ni][0] * inv0, d[mi][ni][1] * inv0);
            *(float2*)(op1 + ni * 8) = make_float2(d[mi][ni][2] * inv1, d[mi][ni][3] * inv1);
        }
    }
}

// =====================================================================
extern "C" void kernel_launch(void* const* d_in, const int* in_sizes, int n_in,
                              void* d_out, int out_size)
{
    const float* h   = (const float*)d_in[0];
    const int*   adj = (const int*)  d_in[1];
    const float* W   = (const float*)d_in[2];
    const float* a   = (const float*)d_in[3];
    float* out = (float*)d_out;

    float *Wh, *E1, *F1, *E2, *F2;
    __half* Whh;
    cudaGetSymbolAddress((void**)&Wh,  g_Wh);
    cudaGetSymbolAddress((void**)&Whh, g_Whh);
    cudaGetSymbolAddress((void**)&E1,  g_E1);
    cudaGetSymbolAddress((void**)&F1,  g_F1);
    cudaGetSymbolAddress((void**)&E2,  g_E2);
    cudaGetSymbolAddress((void**)&F2,  g_F2);

    const int smem1 = 4 * 128 * K1ST * (int)sizeof(uint32_t);   // 73728
    const int smem3 = (2 * 128 * AST + 2 * KJ * BST) * 2 + 256 * 4;  // 38912
    cudaFuncSetAttribute(wh_mma_kernel,  cudaFuncAttributeMaxDynamicSharedMemorySize, smem1);
    cudaFuncSetAttribute(attn_f16_kernel, cudaFuncAttributeMaxDynamicSharedMemorySize, smem3);

    wh_mma_kernel<<<dim3(NTOT / 128, FDIM / 128), 256, smem1>>>(h, W, Wh, Whh);
    fvec_kernel<<<NTOT / 8, 256>>>(Wh, a, E1, F1, E2, F2);
    attn_f16_kernel<<<dim3(NROW / 128, FDIM / 128, NBATCH), 256, smem3>>>(
        adj, Whh, E1, F1, E2, F2, out);
}

// round 5
// speedup vs baseline: 3.6037x; 1.5736x over previous
#include <cuda_runtime.h>
#include <cuda_fp16.h>
#include <cstdint>

// GraphAttentionLayer: B=8, N=2048, Fin=Fout=256
//  K1: Wh = h @ W^T           (mma.sync tf32; writes Wh fp32 + Whh fp16)
//  K2: per-row E1=exp(f1), F1=exp(.2 f1), EF=(exp(f2), exp(.2 f2)) packed
//  K3: mma.sync fp16 m16n8k16: out_i = (sum_j w_ij Wh_j) / (sum_j w_ij)
//      w_ij = adj ? (E2_j > 1/E1_i ? E1_i*E2_j : F1_i*F2_j) : 0  (exact leaky+exp)

#define NROW   2048
#define FDIM   256
#define NBATCH 8
#define NTOT   (NBATCH * NROW)

#define K1ST 36           // K1 u32 smem stride
#define KJ  32
#define NIT (NROW / KJ)   // 64
#define AST 40            // halves stride, w tile row
#define BST 136           // halves stride, Wh tile k-row

// ---------------- scratch ----------------
__device__ float  g_Wh [NTOT * FDIM];   // fp32 for K2
__device__ __half g_Whh[NTOT * FDIM];   // fp16 for K3
__device__ float  g_E1[NTOT], g_F1[NTOT];
__device__ float2 g_EF[NTOT];           // (E2, F2)

// ---------------- helpers ----------------
__device__ __forceinline__ uint32_t to_tf32(float x) {
    uint32_t r; asm("cvt.rna.tf32.f32 %0, %1;" : "=r"(r) : "f"(x)); return r;
}
__device__ __forceinline__ void mma_tf32(float* d, const uint32_t* a, const uint32_t* b) {
    asm volatile(
        "mma.sync.aligned.m16n8k8.row.col.f32.tf32.tf32.f32 "
        "{%0,%1,%2,%3}, {%4,%5,%6,%7}, {%8,%9}, {%0,%1,%2,%3};"
        : "+f"(d[0]), "+f"(d[1]), "+f"(d[2]), "+f"(d[3])
        : "r"(a[0]), "r"(a[1]), "r"(a[2]), "r"(a[3]), "r"(b[0]), "r"(b[1]));
}
__device__ __forceinline__ void mma_f16(float* d, const uint32_t* a, const uint32_t* b) {
    asm volatile(
        "mma.sync.aligned.m16n8k16.row.col.f32.f16.f16.f32 "
        "{%0,%1,%2,%3}, {%4,%5,%6,%7}, {%8,%9}, {%0,%1,%2,%3};"
        : "+f"(d[0]), "+f"(d[1]), "+f"(d[2]), "+f"(d[3])
        : "r"(a[0]), "r"(a[1]), "r"(a[2]), "r"(a[3]), "r"(b[0]), "r"(b[1]));
}
__device__ __forceinline__ void ldm_x4(uint32_t* r, const void* p) {
    uint32_t a = (uint32_t)__cvta_generic_to_shared(p);
    asm volatile("ldmatrix.sync.aligned.m8n8.x4.shared.b16 {%0,%1,%2,%3}, [%4];"
                 : "=r"(r[0]), "=r"(r[1]), "=r"(r[2]), "=r"(r[3]) : "r"(a));
}
__device__ __forceinline__ void ldm_x4_t(uint32_t* r, const void* p) {
    uint32_t a = (uint32_t)__cvta_generic_to_shared(p);
    asm volatile("ldmatrix.sync.aligned.m8n8.x4.trans.shared.b16 {%0,%1,%2,%3}, [%4];"
                 : "=r"(r[0]), "=r"(r[1]), "=r"(r[2]), "=r"(r[3]) : "r"(a));
}

// =====================================================================
// Kernel 1: Wh = h @ W^T via tf32 mma.sync (at legacy-mma ceiling)
// =====================================================================
__global__ void __launch_bounds__(256) wh_mma_kernel(
    const float* __restrict__ h, const float* __restrict__ W,
    float* __restrict__ Wh, __half* __restrict__ Whh)
{
    extern __shared__ uint32_t sm1[];
    uint32_t* sA = sm1;
    uint32_t* sB = sm1 + 2 * 128 * K1ST;

    const int t = threadIdx.x, wid = t >> 5, lid = t & 31;
    const int n0 = blockIdx.x * 128, o0 = blockIdx.y * 128;
    const int r = t >> 1, hfq = t & 1;
    const int wi = wid & 3, wo = wid >> 2;
    const int g = lid >> 2, tig = lid & 3;

    const float* hp = h + (size_t)(n0 + r) * FDIM + hfq * 16;
    const float* wp = W + (size_t)(o0 + r) * FDIM + hfq * 16;

    float d[2][8][4];
#pragma unroll
    for (int mi = 0; mi < 2; mi++)
#pragma unroll
        for (int ni = 0; ni < 8; ni++)
#pragma unroll
            for (int q = 0; q < 4; q++) d[mi][ni][q] = 0.f;

    float4 hr[4], wr[4];

    auto ldg = [&](int it) {
        const int f0 = it * 32;
#pragma unroll
        for (int q = 0; q < 4; q++) {
            hr[q] = *(const float4*)(hp + f0 + q * 4);
            wr[q] = *(const float4*)(wp + f0 + q * 4);
        }
    };
    auto sts = [&](int bf) {
        uint32_t* ab = sA + bf * 128 * K1ST + r * K1ST + hfq * 16;
        uint32_t* bb = sB + bf * 128 * K1ST + r * K1ST + hfq * 16;
#pragma unroll
        for (int q = 0; q < 4; q++) {
            *(uint4*)(ab + q * 4) = make_uint4(to_tf32(hr[q].x), to_tf32(hr[q].y),
                                               to_tf32(hr[q].z), to_tf32(hr[q].w));
            *(uint4*)(bb + q * 4) = make_uint4(to_tf32(wr[q].x), to_tf32(wr[q].y),
                                               to_tf32(wr[q].z), to_tf32(wr[q].w));
        }
    };
    auto mma_phase = [&](int bf) {
        const uint32_t* A = sA + bf * 128 * K1ST;
        const uint32_t* B = sB + bf * 128 * K1ST;
#pragma unroll
        for (int ks = 0; ks < 4; ks++) {
            uint32_t af[2][4];
#pragma unroll
            for (int mi = 0; mi < 2; mi++) {
                const int row = wi * 32 + mi * 16 + g;
                const int kc  = ks * 8 + tig;
                af[mi][0] = A[row * K1ST + kc];
                af[mi][1] = A[(row + 8) * K1ST + kc];
                af[mi][2] = A[row * K1ST + kc + 4];
                af[mi][3] = A[(row + 8) * K1ST + kc + 4];
            }
            uint32_t bfr[8][2];
#pragma unroll
            for (int ni = 0; ni < 8; ni++) {
                const int col = wo * 64 + ni * 8 + g;
                const int kc  = ks * 8 + tig;
                bfr[ni][0] = B[col * K1ST + kc];
                bfr[ni][1] = B[col * K1ST + kc + 4];
            }
#pragma unroll
            for (int mi = 0; mi < 2; mi++)
#pragma unroll
                for (int ni = 0; ni < 8; ni++)
                    mma_tf32(d[mi][ni], af[mi], bfr[ni]);
        }
    };

    ldg(0); sts(0); __syncthreads();
    for (int it = 0; it < 8; it++) {
        if (it + 1 < 8) ldg(it + 1);
        mma_phase(it & 1);
        if (it + 1 < 8) sts((it + 1) & 1);
        __syncthreads();
    }

#pragma unroll
    for (int mi = 0; mi < 2; mi++) {
        const int r0 = wi * 32 + mi * 16 + g;
        const int r1 = r0 + 8;
        float*  o0p = Wh + (size_t)(n0 + r0) * FDIM + o0 + wo * 64 + tig * 2;
        float*  o1p = Wh + (size_t)(n0 + r1) * FDIM + o0 + wo * 64 + tig * 2;
        __half* h0p = Whh + (size_t)(n0 + r0) * FDIM + o0 + wo * 64 + tig * 2;
        __half* h1p = Whh + (size_t)(n0 + r1) * FDIM + o0 + wo * 64 + tig * 2;
#pragma unroll
        for (int ni = 0; ni < 8; ni++) {
            *(float2*)(o0p + ni * 8) = make_float2(d[mi][ni][0], d[mi][ni][1]);
            *(float2*)(o1p + ni * 8) = make_float2(d[mi][ni][2], d[mi][ni][3]);
            *(__half2*)(h0p + ni * 8) =
                __float22half2_rn(make_float2(d[mi][ni][0], d[mi][ni][1]));
            *(__half2*)(h1p + ni * 8) =
                __float22half2_rn(make_float2(d[mi][ni][2], d[mi][ni][3]));
        }
    }
}

// =====================================================================
// Kernel 2: per-row f1,f2 -> E1, F1, (E2,F2) packed
// =====================================================================
__global__ void __launch_bounds__(256) fvec_kernel(
    const float* __restrict__ Wh, const float* __restrict__ a,
    float* __restrict__ E1, float* __restrict__ F1, float2* __restrict__ EF)
{
    const int row  = blockIdx.x * 8 + (threadIdx.x >> 5);
    const int lane = threadIdx.x & 31;
    const float4* wr = (const float4*)(Wh + (size_t)row * FDIM);
    const float4* a1 = (const float4*)a;
    const float4* a2 = (const float4*)(a + FDIM);

    float4 x0 = wr[lane], x1 = wr[lane + 32];
    float4 p0 = a1[lane], p1 = a1[lane + 32];
    float4 q0 = a2[lane], q1 = a2[lane + 32];

    float s1 = x0.x * p0.x + x0.y * p0.y + x0.z * p0.z + x0.w * p0.w
             + x1.x * p1.x + x1.y * p1.y + x1.z * p1.z + x1.w * p1.w;
    float s2 = x0.x * q0.x + x0.y * q0.y + x0.z * q0.z + x0.w * q0.w
             + x1.x * q1.x + x1.y * q1.y + x1.z * q1.z + x1.w * q1.w;
#pragma unroll
    for (int o = 16; o; o >>= 1) {
        s1 += __shfl_xor_sync(0xFFFFFFFFu, s1, o);
        s2 += __shfl_xor_sync(0xFFFFFFFFu, s2, o);
    }
    if (lane == 0) {
        E1[row] = __expf(s1);
        F1[row] = __expf(0.2f * s1);
        EF[row] = make_float2(__expf(s2), __expf(0.2f * s2));
    }
}

// =====================================================================
// Kernel 3: fp16 m16n8k16 attention. Block 128i x 128o, j-chunks of 32.
// (E2,F2) staged once into smem; adj/Whh prefetched; 2 blocks/SM.
// =====================================================================
// smem bytes: A 2*128*40*2=20480 | B 2*32*136*2=17408 | EF 2048*8=16384 | den 1024
#define SMB_A  0
#define SMB_B  20480
#define SMB_EF 37888
#define SMB_DN 54272
#define SMB_SZ 55296

__global__ void __launch_bounds__(256, 2) attn_f16_kernel(
    const int*  __restrict__ adj,
    const __half* __restrict__ Whh,
    const float* __restrict__ E1, const float* __restrict__ F1,
    const float2* __restrict__ EF,
    float* __restrict__ out)
{
    extern __shared__ char smc[];
    __half* smA = (__half*)(smc + SMB_A);     // [2][128][AST]
    __half* smB = (__half*)(smc + SMB_B);     // [2][32][BST]
    float2* sEF = (float2*)(smc + SMB_EF);    // [2048]
    float*  den = (float*)(smc + SMB_DN);     // [256]

    const int t = threadIdx.x, wid = t >> 5, lid = t & 31;
    const int bz = blockIdx.z;
    const int i0 = blockIdx.x * 128;
    const int o0 = blockIdx.y * 128;

    const int r = t >> 1, hf = t & 1;             // w-gen: row r, j-half hf*16
    const int krow = t >> 3, kcol = (t & 7) * 16; // B staging roles
    const int wi = wid & 3, wo = wid >> 2;
    const int g = lid >> 2, tig = lid & 3;

    // stage (E2,F2) for this batch into smem (one time)
    {
        const float4* src = (const float4*)(EF + bz * NROW);
        float4* dst = (float4*)sEF;
#pragma unroll
        for (int q = 0; q < 4; q++) dst[t + q * 256] = src[t + q * 256];
    }

    const int row_g = bz * NROW + i0 + r;
    const int*    adjp = adj + (size_t)row_g * NROW + hf * 16;
    const __half* whp  = Whh + (size_t)(bz * NROW + krow) * FDIM + o0 + kcol;
    const float   E1r  = E1[row_g], F1r = F1[row_g];
    const float   tinv = __frcp_rn(E1r);          // s>0  <=>  E2_j > 1/E1_i

    float d[2][8][4];
#pragma unroll
    for (int mi = 0; mi < 2; mi++)
#pragma unroll
        for (int ni = 0; ni < 8; ni++)
#pragma unroll
            for (int q = 0; q < 4; q++) d[mi][ni][q] = 0.f;

    float dn = 0.f;
    int4  adjr[4];
    uint4 hh0, hh1;

    auto ldg = [&](int c) {
        const int j0 = c * KJ;
#pragma unroll
        for (int q = 0; q < 4; q++)
            adjr[q] = *(const int4*)(adjp + j0 + q * 4);
        hh0 = *(const uint4*)(whp + (size_t)j0 * FDIM);
        hh1 = *(const uint4*)(whp + (size_t)j0 * FDIM + 8);
    };

    auto gen_sts = [&](int bf, int c) {
        const int j0 = c * KJ + hf * 16;
        __half* bb = smB + bf * (KJ * BST) + krow * BST + kcol;
        *(uint4*)bb       = hh0;
        *(uint4*)(bb + 8) = hh1;
        uint32_t h2a[8];
#pragma unroll
        for (int q = 0; q < 4; q++) {
            const int* am = (const int*)&adjr[q];
            float w4[4];
#pragma unroll
            for (int e = 0; e < 4; e++) {
                const float2 ef = sEF[j0 + q * 4 + e];
                const float w = am[e] ? (ef.x > tinv ? E1r * ef.x : F1r * ef.y) : 0.f;
                dn += w;
                w4[e] = w;
            }
            __half2 p0 = __float22half2_rn(make_float2(w4[0], w4[1]));
            __half2 p1 = __float22half2_rn(make_float2(w4[2], w4[3]));
            h2a[q * 2 + 0] = *(uint32_t*)&p0;
            h2a[q * 2 + 1] = *(uint32_t*)&p1;
        }
        __half* ab = smA + bf * (128 * AST) + r * AST + hf * 16;
        *(uint4*)ab       = *(uint4*)&h2a[0];
        *(uint4*)(ab + 8) = *(uint4*)&h2a[4];
    };

    auto mma_phase = [&](int bf) {
        const __half* A = smA + bf * (128 * AST);
        const __half* B = smB + bf * (KJ * BST);
#pragma unroll
        for (int ks = 0; ks < 2; ks++) {
            uint32_t af[2][4];
#pragma unroll
            for (int mi = 0; mi < 2; mi++)
                ldm_x4(af[mi], A + (wi * 32 + mi * 16 + (lid & 15)) * AST
                               + ks * 16 + (lid >> 4) * 8);
            uint32_t bf4[4][4];
#pragma unroll
            for (int np = 0; np < 4; np++)
                ldm_x4_t(bf4[np], B + (ks * 16 + (lid & 7) + ((lid >> 3) & 1) * 8) * BST
                                  + wo * 64 + np * 16 + (lid >> 4) * 8);
#pragma unroll
            for (int mi = 0; mi < 2; mi++)
#pragma unroll
                for (int ni = 0; ni < 8; ni++)
                    mma_f16(d[mi][ni], af[mi], &bf4[ni >> 1][(ni & 1) * 2]);
        }
    };

    ldg(0);
    __syncthreads();   // sEF visible
    for (int c = 0; c < NIT; c++) {
        const int bf = c & 1;
        gen_sts(bf, c);
        __syncthreads();
        if (c + 1 < NIT) ldg(c + 1);
        mma_phase(bf);
    }

    den[t] = dn;                      // den[2*row + hf]
    __syncthreads();

#pragma unroll
    for (int mi = 0; mi < 2; mi++) {
        const int r0 = wi * 32 + mi * 16 + g;
        const int r1 = r0 + 8;
        const float inv0 = 1.0f / (den[2 * r0] + den[2 * r0 + 1]);
        const float inv1 = 1.0f / (den[2 * r1] + den[2 * r1 + 1]);
        float* op0 = out + (size_t)(bz * NROW + i0 + r0) * FDIM + o0 + wo * 64 + tig * 2;
        float* op1 = out + (size_t)(bz * NROW + i0 + r1) * FDIM + o0 + wo * 64 + tig * 2;
#pragma unroll
        for (int ni = 0; ni < 8; ni++) {
            *(float2*)(op0 + ni * 8) = make_float2(d[mi][ni][0] * inv0, d[mi][ni][1] * inv0);
            *(float2*)(op1 + ni * 8) = make_float2(d[mi][ni][2] * inv1, d[mi][ni][3] * inv1);
        }
    }
}

// =====================================================================
extern "C" void kernel_launch(void* const* d_in, const int* in_sizes, int n_in,
                              void* d_out, int out_size)
{
    const float* h   = (const float*)d_in[0];
    const int*   adj = (const int*)  d_in[1];
    const float* W   = (const float*)d_in[2];
    const float* a   = (const float*)d_in[3];
    float* out = (float*)d_out;

    float *Wh, *E1, *F1;
    float2* EFp;
    __half* Whh;
    cudaGetSymbolAddress((void**)&Wh,  g_Wh);
    cudaGetSymbolAddress((void**)&Whh, g_Whh);
    cudaGetSymbolAddress((void**)&E1,  g_E1);
    cudaGetSymbolAddress((void**)&F1,  g_F1);
    cudaGetSymbolAddress((void**)&EFp, g_EF);

    const int smem1 = 4 * 128 * K1ST * (int)sizeof(uint32_t);   // 73728
    cudaFuncSetAttribute(wh_mma_kernel,   cudaFuncAttributeMaxDynamicSharedMemorySize, smem1);
    cudaFuncSetAttribute(attn_f16_kernel, cudaFuncAttributeMaxDynamicSharedMemorySize, SMB_SZ);

    wh_mma_kernel<<<dim3(NTOT / 128, FDIM / 128), 256, smem1>>>(h, W, Wh, Whh);
    fvec_kernel<<<NTOT / 8, 256>>>(Wh, a, E1, F1, EFp);
    attn_f16_kernel<<<dim3(NROW / 128, FDIM / 128, NBATCH), 256, SMB_SZ>>>(
        adj, Whh, E1, F1, EFp, out);
}

// round 7
// speedup vs baseline: 4.0204x; 1.1157x over previous
#include <cuda_runtime.h>
#include <cuda_fp16.h>
#include <cstdint>

// GraphAttentionLayer: B=8, N=2048, Fin=Fout=256
//  K1: Wh = h @ W^T           (mma.sync tf32; writes Wh fp32 + Whh fp16)
//  K2: per-row E1=exp(f1), F1=exp(.2 f1), EF=(exp(f2), exp(.2 f2))
//  K3: fp16 m16n8k16 attention, 128i x 256o blocks, cp.async 4-stage pipeline
//      w_ij = adj ? (E2_j > 1/E1_i ? E1_i*E2_j : F1_i*F2_j) : 0  (exact leaky+exp)

#define NROW   2048
#define FDIM   256
#define NBATCH 8
#define NTOT   (NBATCH * NROW)

#define K1ST 36
#define KJ   32
#define NIT  (NROW / KJ)   // 64

// ---------------- scratch ----------------
__device__ float  g_Wh [NTOT * FDIM];
__device__ __half g_Whh[NTOT * FDIM];
__device__ float  g_E1[NTOT], g_F1[NTOT];
__device__ float2 g_EF[NTOT];

// ---------------- helpers ----------------
__device__ __forceinline__ uint32_t to_tf32(float x) {
    uint32_t r; asm("cvt.rna.tf32.f32 %0, %1;" : "=r"(r) : "f"(x)); return r;
}
__device__ __forceinline__ void mma_tf32(float* d, const uint32_t* a, const uint32_t* b) {
    asm volatile(
        "mma.sync.aligned.m16n8k8.row.col.f32.tf32.tf32.f32 "
        "{%0,%1,%2,%3}, {%4,%5,%6,%7}, {%8,%9}, {%0,%1,%2,%3};"
        : "+f"(d[0]), "+f"(d[1]), "+f"(d[2]), "+f"(d[3])
        : "r"(a[0]), "r"(a[1]), "r"(a[2]), "r"(a[3]), "r"(b[0]), "r"(b[1]));
}
__device__ __forceinline__ void mma_f16(float* d, const uint32_t* a, const uint32_t* b) {
    asm volatile(
        "mma.sync.aligned.m16n8k16.row.col.f32.f16.f16.f32 "
        "{%0,%1,%2,%3}, {%4,%5,%6,%7}, {%8,%9}, {%0,%1,%2,%3};"
        : "+f"(d[0]), "+f"(d[1]), "+f"(d[2]), "+f"(d[3])
        : "r"(a[0]), "r"(a[1]), "r"(a[2]), "r"(a[3]), "r"(b[0]), "r"(b[1]));
}
__device__ __forceinline__ void ldm_x4(uint32_t* r, const void* p) {
    uint32_t a = (uint32_t)__cvta_generic_to_shared(p);
    asm volatile("ldmatrix.sync.aligned.m8n8.x4.shared.b16 {%0,%1,%2,%3}, [%4];"
                 : "=r"(r[0]), "=r"(r[1]), "=r"(r[2]), "=r"(r[3]) : "r"(a));
}
__device__ __forceinline__ void ldm_x4_t(uint32_t* r, const void* p) {
    uint32_t a = (uint32_t)__cvta_generic_to_shared(p);
    asm volatile("ldmatrix.sync.aligned.m8n8.x4.trans.shared.b16 {%0,%1,%2,%3}, [%4];"
                 : "=r"(r[0]), "=r"(r[1]), "=r"(r[2]), "=r"(r[3]) : "r"(a));
}
__device__ __forceinline__ void cp_async16(void* dst, const void* src) {
    uint32_t d = (uint32_t)__cvta_generic_to_shared(dst);
    asm volatile("cp.async.cg.shared.global [%0], [%1], 16;" :: "r"(d), "l"(src));
}
#define CP_COMMIT() asm volatile("cp.async.commit_group;" ::: "memory")
#define CP_WAIT2()  asm volatile("cp.async.wait_group 2;" ::: "memory")

// =====================================================================
// Kernel 1: Wh = h @ W^T via tf32 mma.sync
// =====================================================================
__global__ void __launch_bounds__(256) wh_mma_kernel(
    const float* __restrict__ h, const float* __restrict__ W,
    float* __restrict__ Wh, __half* __restrict__ Whh)
{
    extern __shared__ uint32_t sm1[];
    uint32_t* sA = sm1;
    uint32_t* sB = sm1 + 2 * 128 * K1ST;

    const int t = threadIdx.x, wid = t >> 5, lid = t & 31;
    const int n0 = blockIdx.x * 128, o0 = blockIdx.y * 128;
    const int r = t >> 1, hfq = t & 1;
    const int wi = wid & 3, wo = wid >> 2;
    const int g = lid >> 2, tig = lid & 3;

    const float* hp = h + (size_t)(n0 + r) * FDIM + hfq * 16;
    const float* wp = W + (size_t)(o0 + r) * FDIM + hfq * 16;

    float d[2][8][4];
#pragma unroll
    for (int mi = 0; mi < 2; mi++)
#pragma unroll
        for (int ni = 0; ni < 8; ni++)
#pragma unroll
            for (int q = 0; q < 4; q++) d[mi][ni][q] = 0.f;

    float4 hr[4], wr[4];

    auto ldg = [&](int it) {
        const int f0 = it * 32;
#pragma unroll
        for (int q = 0; q < 4; q++) {
            hr[q] = *(const float4*)(hp + f0 + q * 4);
            wr[q] = *(const float4*)(wp + f0 + q * 4);
        }
    };
    auto sts = [&](int bf) {
        uint32_t* ab = sA + bf * 128 * K1ST + r * K1ST + hfq * 16;
        uint32_t* bb = sB + bf * 128 * K1ST + r * K1ST + hfq * 16;
#pragma unroll
        for (int q = 0; q < 4; q++) {
            *(uint4*)(ab + q * 4) = make_uint4(to_tf32(hr[q].x), to_tf32(hr[q].y),
                                               to_tf32(hr[q].z), to_tf32(hr[q].w));
            *(uint4*)(bb + q * 4) = make_uint4(to_tf32(wr[q].x), to_tf32(wr[q].y),
                                               to_tf32(wr[q].z), to_tf32(wr[q].w));
        }
    };
    auto mma_phase = [&](int bf) {
        const uint32_t* A = sA + bf * 128 * K1ST;
        const uint32_t* B = sB + bf * 128 * K1ST;
#pragma unroll
        for (int ks = 0; ks < 4; ks++) {
            uint32_t af[2][4];
#pragma unroll
            for (int mi = 0; mi < 2; mi++) {
                const int row = wi * 32 + mi * 16 + g;
                const int kc  = ks * 8 + tig;
                af[mi][0] = A[row * K1ST + kc];
                af[mi][1] = A[(row + 8) * K1ST + kc];
                af[mi][2] = A[row * K1ST + kc + 4];
                af[mi][3] = A[(row + 8) * K1ST + kc + 4];
            }
            uint32_t bfr[8][2];
#pragma unroll
            for (int ni = 0; ni < 8; ni++) {
                const int col = wo * 64 + ni * 8 + g;
                const int kc  = ks * 8 + tig;
                bfr[ni][0] = B[col * K1ST + kc];
                bfr[ni][1] = B[col * K1ST + kc + 4];
            }
#pragma unroll
            for (int mi = 0; mi < 2; mi++)
#pragma unroll
                for (int ni = 0; ni < 8; ni++)
                    mma_tf32(d[mi][ni], af[mi], bfr[ni]);
        }
    };

    ldg(0); sts(0); __syncthreads();
    for (int it = 0; it < 8; it++) {
        if (it + 1 < 8) ldg(it + 1);
        mma_phase(it & 1);
        if (it + 1 < 8) sts((it + 1) & 1);
        __syncthreads();
    }

#pragma unroll
    for (int mi = 0; mi < 2; mi++) {
        const int r0 = wi * 32 + mi * 16 + g;
        const int r1 = r0 + 8;
        float*  o0p = Wh + (size_t)(n0 + r0) * FDIM + o0 + wo * 64 + tig * 2;
        float*  o1p = Wh + (size_t)(n0 + r1) * FDIM + o0 + wo * 64 + tig * 2;
        __half* h0p = Whh + (size_t)(n0 + r0) * FDIM + o0 + wo * 64 + tig * 2;
        __half* h1p = Whh + (size_t)(n0 + r1) * FDIM + o0 + wo * 64 + tig * 2;
#pragma unroll
        for (int ni = 0; ni < 8; ni++) {
            *(float2*)(o0p + ni * 8) = make_float2(d[mi][ni][0], d[mi][ni][1]);
            *(float2*)(o1p + ni * 8) = make_float2(d[mi][ni][2], d[mi][ni][3]);
            *(__half2*)(h0p + ni * 8) =
                __float22half2_rn(make_float2(d[mi][ni][0], d[mi][ni][1]));
            *(__half2*)(h1p + ni * 8) =
                __float22half2_rn(make_float2(d[mi][ni][2], d[mi][ni][3]));
        }
    }
}

// =====================================================================
// Kernel 2: per-row f1,f2 -> E1, F1, (E2,F2)
// =====================================================================
__global__ void __launch_bounds__(256) fvec_kernel(
    const float* __restrict__ Wh, const float* __restrict__ a,
    float* __restrict__ E1, float* __restrict__ F1, float2* __restrict__ EF)
{
    const int row  = blockIdx.x * 8 + (threadIdx.x >> 5);
    const int lane = threadIdx.x & 31;
    const float4* wr = (const float4*)(Wh + (size_t)row * FDIM);
    const float4* a1 = (const float4*)a;
    const float4* a2 = (const float4*)(a + FDIM);

    float4 x0 = wr[lane], x1 = wr[lane + 32];
    float4 p0 = a1[lane], p1 = a1[lane + 32];
    float4 q0 = a2[lane], q1 = a2[lane + 32];

    float s1 = x0.x * p0.x + x0.y * p0.y + x0.z * p0.z + x0.w * p0.w
             + x1.x * p1.x + x1.y * p1.y + x1.z * p1.z + x1.w * p1.w;
    float s2 = x0.x * q0.x + x0.y * q0.y + x0.z * q0.z + x0.w * q0.w
             + x1.x * q1.x + x1.y * q1.y + x1.z * q1.z + x1.w * q1.w;
#pragma unroll
    for (int o = 16; o; o >>= 1) {
        s1 += __shfl_xor_sync(0xFFFFFFFFu, s1, o);
        s2 += __shfl_xor_sync(0xFFFFFFFFu, s2, o);
    }
    if (lane == 0) {
        E1[row] = __expf(s1);
        F1[row] = __expf(0.2f * s1);
        EF[row] = make_float2(__expf(s2), __expf(0.2f * s2));
    }
}

// =====================================================================
// Kernel 3: fp16 mma attention, 128i x 256o blocks, 512 threads,
// cp.async 4-stage adj/Whh pipeline, single barrier per chunk.
// =====================================================================
#define AST3 40            // A tile row stride (halves): 32 + 8 pad
#define BST3 264           // B tile k-row stride (halves): 256 + 8 pad
// smem layout (bytes)
#define OFF_A   0          // A: 2 * 128 * 40 halves          = 20480
#define OFF_B   20480      // B ring: 4 * 32 * 264 halves     = 67584
#define OFF_ADJ 88064      // adj ring: 4 * 128 * 32 ints     = 65536
#define OFF_EF  153600     // EF: 2048 * float2               = 16384
#define OFF_DN  169984     // den: 512 * float                =  2048
#define SM3_SZ  172032

__global__ void __launch_bounds__(512, 1) attn_f16_kernel(
    const int*  __restrict__ adj,
    const __half* __restrict__ Whh,
    const float* __restrict__ E1, const float* __restrict__ F1,
    const float2* __restrict__ EF,
    float* __restrict__ out)
{
    extern __shared__ char smc[];
    __half* smA = (__half*)(smc + OFF_A);
    __half* smB = (__half*)(smc + OFF_B);
    char*   smJ = smc + OFF_ADJ;
    float2* sEF = (float2*)(smc + OFF_EF);
    float*  den = (float*)(smc + OFF_DN);

    const int t = threadIdx.x, wid = t >> 5, lid = t & 31;
    const int bz = blockIdx.y, i0 = blockIdx.x * 128;
    const int r  = t >> 2, jq = (t & 3) * 8;     // w-gen: row r, 8 j's
    const int wi = wid & 3, wo = wid >> 2;       // warp tile: rows wi*32, cols wo*64
    const int g  = lid >> 2, tig = lid & 3;

    // ---- stage (E2,F2) once ----
    {
        const float4* src = (const float4*)(EF + bz * NROW);
        float4* dst = (float4*)sEF;
        dst[t]       = src[t];
        dst[t + 512] = src[t + 512];
    }

    const int row_g = bz * NROW + i0 + r;
    const float E1r  = E1[row_g], F1r = F1[row_g];
    const float tinv = __frcp_rn(E1r);           // s>0  <=>  E2_j > 1/E1_i

    // cp.async source bases
    // adj: this thread copies row r, bytes [(t&3)*32, +32) of each 128B chunk-row
    const char* adj_src = (const char*)(adj + (size_t)row_g * NROW) + (t & 3) * 32;
    // Whh: this thread copies k-row (t&31), byte segs (t>>5)*16 and +256
    const char* whh_src = (const char*)(Whh + (size_t)(bz * NROW + (t & 31)) * FDIM)
                          + (t >> 5) * 16;

    auto stage = [&](int c) {
        const int slot = c & 3;
        {
            char* dst = smJ + slot * 16384 + r * 128 + (t & 3) * 32;
            const char* src = adj_src + (size_t)c * 128;
            cp_async16(dst, src);
            cp_async16(dst + 16, src + 16);
        }
        {
            char* dst = (char*)smB + slot * (32 * BST3 * 2)
                        + (t & 31) * (BST3 * 2) + (t >> 5) * 16;
            const char* src = whh_src + (size_t)c * (KJ * FDIM * 2);
            cp_async16(dst, src);
            cp_async16(dst + 256, src + 256);
        }
    };

    float d[2][8][4];
#pragma unroll
    for (int mi = 0; mi < 2; mi++)
#pragma unroll
        for (int ni = 0; ni < 8; ni++)
#pragma unroll
            for (int q = 0; q < 4; q++) d[mi][ni][q] = 0.f;
    float dn = 0.f;

    auto gen = [&](int c) {
        const int slot = c & 3, bf = c & 1;
        const int4* ap = (const int4*)(smJ + slot * 16384 + r * 128 + jq * 4);
        int4 a0 = ap[0], a1 = ap[1];
        const float2* efp = sEF + c * KJ + jq;
        float w[8];
        const int* am0 = (const int*)&a0;
        const int* am1 = (const int*)&a1;
#pragma unroll
        for (int e = 0; e < 4; e++) {
            const float2 ef = efp[e];
            const float v = am0[e] ? (ef.x > tinv ? E1r * ef.x : F1r * ef.y) : 0.f;
            dn += v; w[e] = v;
        }
#pragma unroll
        for (int e = 0; e < 4; e++) {
            const float2 ef = efp[4 + e];
            const float v = am1[e] ? (ef.x > tinv ? E1r * ef.x : F1r * ef.y) : 0.f;
            dn += v; w[4 + e] = v;
        }
        __half2 p0 = __float22half2_rn(make_float2(w[0], w[1]));
        __half2 p1 = __float22half2_rn(make_float2(w[2], w[3]));
        __half2 p2 = __float22half2_rn(make_float2(w[4], w[5]));
        __half2 p3 = __float22half2_rn(make_float2(w[6], w[7]));
        uint4 pk = make_uint4(*(uint32_t*)&p0, *(uint32_t*)&p1,
                              *(uint32_t*)&p2, *(uint32_t*)&p3);
        *(uint4*)(smA + bf * (128 * AST3) + r * AST3 + jq) = pk;
    };

    auto mma_phase = [&](int c) {
        const __half* A = smA + (c & 1) * (128 * AST3);
        const __half* B = smB + (c & 3) * (32 * BST3);
#pragma unroll
        for (int ks = 0; ks < 2; ks++) {
            uint32_t af[2][4];
#pragma unroll
            for (int mi = 0; mi < 2; mi++)
                ldm_x4(af[mi], A + (wi * 32 + mi * 16 + (lid & 15)) * AST3
                               + ks * 16 + (lid >> 4) * 8);
            uint32_t bf4[4][4];
#pragma unroll
            for (int np = 0; np < 4; np++)
                ldm_x4_t(bf4[np], B + (ks * 16 + (lid & 7) + ((lid >> 3) & 1) * 8) * BST3
                                  + wo * 64 + np * 16 + (lid >> 4) * 8);
#pragma unroll
            for (int mi = 0; mi < 2; mi++)
#pragma unroll
                for (int ni = 0; ni < 8; ni++)
                    mma_f16(d[mi][ni], af[mi], &bf4[ni >> 1][(ni & 1) * 2]);
        }
    };

    // ---- pipeline ----
    stage(0); CP_COMMIT();
    stage(1); CP_COMMIT();
    stage(2); CP_COMMIT();
    __syncthreads();                 // sEF visible

    for (int c = 0; c < NIT; c++) {
        CP_WAIT2();                  // group c complete (self-visible adj segs)
        gen(c);                      // A[c&1] <- w ; reads adj slot c&3 (own segs)
        __syncthreads();             // A + B slot c visible; mma(c-1) fully done
        if (c + 3 < NIT) stage(c + 3);
        CP_COMMIT();                 // keep group numbering uniform
        mma_phase(c);
    }

    den[t] = dn;
    __syncthreads();

    // ---- epilogue ----
#pragma unroll
    for (int mi = 0; mi < 2; mi++) {
        const int r0 = wi * 32 + mi * 16 + g;
        const int r1 = r0 + 8;
        const float inv0 = 1.0f / (den[4 * r0] + den[4 * r0 + 1]
                                 + den[4 * r0 + 2] + den[4 * r0 + 3]);
        const float inv1 = 1.0f / (den[4 * r1] + den[4 * r1 + 1]
                                 + den[4 * r1 + 2] + den[4 * r1 + 3]);
        float* op0 = out + (size_t)(bz * NROW + i0 + r0) * FDIM + wo * 64 + tig * 2;
        float* op1 = out + (size_t)(bz * NROW + i0 + r1) * FDIM + wo * 64 + tig * 2;
#pragma unroll
        for (int ni = 0; ni < 8; ni++) {
            *(float2*)(op0 + ni * 8) = make_float2(d[mi][ni][0] * inv0, d[mi][ni][1] * inv0);
            *(float2*)(op1 + ni * 8) = make_float2(d[mi][ni][2] * inv1, d[mi][ni][3] * inv1);
        }
    }
}

// =====================================================================
extern "C" void kernel_launch(void* const* d_in, const int* in_sizes, int n_in,
                              void* d_out, int out_size)
{
    const float* h   = (const float*)d_in[0];
    const int*   adj = (const int*)  d_in[1];
    const float* W   = (const float*)d_in[2];
    const float* a   = (const float*)d_in[3];
    float* out = (float*)d_out;

    float *Wh, *E1, *F1;
    float2* EFp;
    __half* Whh;
    cudaGetSymbolAddress((void**)&Wh,  g_Wh);
    cudaGetSymbolAddress((void**)&Whh, g_Whh);
    cudaGetSymbolAddress((void**)&E1,  g_E1);
    cudaGetSymbolAddress((void**)&F1,  g_F1);
    cudaGetSymbolAddress((void**)&EFp, g_EF);

    const int smem1 = 4 * 128 * K1ST * (int)sizeof(uint32_t);   // 73728
    cudaFuncSetAttribute(wh_mma_kernel,   cudaFuncAttributeMaxDynamicSharedMemorySize, smem1);
    cudaFuncSetAttribute(attn_f16_kernel, cudaFuncAttributeMaxDynamicSharedMemorySize, SM3_SZ);

    wh_mma_kernel<<<dim3(NTOT / 128, FDIM / 128), 256, smem1>>>(h, W, Wh, Whh);
    fvec_kernel<<<NTOT / 8, 256>>>(Wh, a, E1, F1, EFp);
    attn_f16_kernel<<<dim3(NROW / 128, NBATCH), 512, SM3_SZ>>>(
        adj, Whh, E1, F1, EFp, out);
}